// round 4
// baseline (speedup 1.0000x reference)
#include <cuda_runtime.h>
#include <cstdint>

#define BATCH   32768
#define PAIRS   (BATCH / 2)      // 16384
#define TSTEPS  60
#define FIN     26
#define HID     24
#define G3      (3 * HID)        // 72
#define RPH     (HID / 2)        // 12 rows per half-thread
#define WSTRIDE 26               // padded u64 stride for both weight arrays

typedef unsigned long long u64;

// ---------- packed f32x2 helpers ----------
__device__ __forceinline__ u64 pk(float a, float b) {
    u64 r;
    asm("mov.b64 %0, {%1, %2};" : "=l"(r) : "f"(a), "f"(b));
    return r;
}
__device__ __forceinline__ void upk(u64 v, float& a, float& b) {
    asm("mov.b64 {%0, %1}, %2;" : "=f"(a), "=f"(b) : "l"(v));
}
__device__ __forceinline__ void ffma2_ip(u64& acc, u64 a, u64 b) {
    asm("fma.rn.f32x2 %0, %1, %2, %0;" : "+l"(acc) : "l"(a), "l"(b));
}

// ---------- fast activations (≈1e-6 rel err) ----------
__device__ __forceinline__ float sigmoidf_(float x) {
    return __fdividef(1.0f, 1.0f + __expf(-x));
}
__device__ __forceinline__ float tanhf_(float x) {
    float s = __fdividef(2.0f, 1.0f + __expf(-2.0f * x));
    return s - 1.0f;
}

__global__ void __launch_bounds__(224, 1)
_ShotRNN_90417651516362_kernel(
    const float* __restrict__ x,      // [B, T, 26]
    const float* __restrict__ w_ih,   // [72, 26]
    const float* __restrict__ w_hh,   // [72, 24]
    const float* __restrict__ b_ih,   // [72]
    const float* __restrict__ b_hh,   // [72]
    const float* __restrict__ fc1_w,  // [8, 24]
    const float* __restrict__ fc1_b,  // [8]
    const float* __restrict__ fc2_w,  // [4, 8]
    const float* __restrict__ fc2_b,  // [4]
    float* __restrict__ out)          // [B, 4]
{
    // Duplicated-pair (w,w) weights; both arrays padded to stride 26 u64 so
    // the two cooperating halves (rows r and r+12) hit different banks:
    // 12*26*8 = 2496 B -> +16 banks. 26*8 = 208 B keeps 16B alignment.
    __shared__ __align__(16) u64 s_wih[G3 * WSTRIDE];
    __shared__ __align__(16) u64 s_whh[G3 * WSTRIDE];
    __shared__ __align__(16) u64 s_br[HID];
    __shared__ __align__(16) u64 s_bz[HID];
    __shared__ __align__(16) u64 s_bnx[HID];
    __shared__ __align__(16) u64 s_bnh[HID];
    __shared__ __align__(16) u64 s_f1w[8 * HID];
    __shared__ __align__(16) u64 s_f1b[8];
    __shared__ __align__(16) u64 s_f2w[4 * 8];
    __shared__ __align__(16) u64 s_f2b[4];

    const int tid = threadIdx.x;
    const int blk = blockDim.x;

    for (int i = tid; i < G3 * FIN; i += blk) {
        int r = i / FIN, c = i % FIN;
        float w = w_ih[i];
        s_wih[r * WSTRIDE + c] = pk(w, w);
    }
    for (int i = tid; i < G3 * HID; i += blk) {
        int r = i / HID, c = i % HID;
        float w = w_hh[i];
        s_whh[r * WSTRIDE + c] = pk(w, w);
    }
    for (int i = tid; i < HID; i += blk) {
        float br = b_ih[i]         + b_hh[i];         s_br[i]  = pk(br, br);
        float bz = b_ih[HID + i]   + b_hh[HID + i];   s_bz[i]  = pk(bz, bz);
        float bx = b_ih[2*HID + i];                   s_bnx[i] = pk(bx, bx);
        float bh = b_hh[2*HID + i];                   s_bnh[i] = pk(bh, bh);
    }
    for (int i = tid; i < 8 * HID; i += blk) { float w = fc1_w[i]; s_f1w[i] = pk(w, w); }
    for (int i = tid; i < 8; i += blk)       { float w = fc1_b[i]; s_f1b[i] = pk(w, w); }
    for (int i = tid; i < 32; i += blk)      { float w = fc2_w[i]; s_f2w[i] = pk(w, w); }
    for (int i = tid; i < 4; i += blk)       { float w = fc2_b[i]; s_f2b[i] = pk(w, w); }
    __syncthreads();

    // Worker mapping: two consecutive threads (same warp, lanes 2k/2k+1)
    // cooperate on one batch-pair. Warp-aligned activity boundary.
    const int worker = blockIdx.x * blk + tid;
    const int pair = worker >> 1;
    const int half = worker & 1;
    if (pair >= PAIRS) return;

    const int base  = half * RPH;       // my gate rows:   base .. base+11
    const int obase = RPH - base;       // partner's rows: obase .. obase+11

    const float* xr0 = x + (size_t)(2 * pair) * (TSTEPS * FIN);
    const float* xr1 = xr0 + (TSTEPS * FIN);

    u64 h[HID];
#pragma unroll
    for (int i = 0; i < HID; i++) h[i] = 0ull;

#pragma unroll 1
    for (int t = 0; t < TSTEPS; t++) {
        // Both halves load the full x rows for the pair (DRAM is ~3% busy).
        float2 v0[FIN / 2], v1[FIN / 2];
        const float2* p0 = (const float2*)(xr0 + t * FIN);
        const float2* p1 = (const float2*)(xr1 + t * FIN);
#pragma unroll
        for (int f = 0; f < FIN / 2; f++) {
            v0[f] = __ldg(p0 + f);
            v1[f] = __ldg(p1 + f);
        }
        u64 xp[FIN];
#pragma unroll
        for (int f = 0; f < FIN / 2; f++) {
            xp[2*f]   = pk(v0[f].x, v1[f].x);
            xp[2*f+1] = pk(v0[f].y, v1[f].y);
        }

        u64 hn[RPH];
#pragma unroll 2
        for (int i = 0; i < RPH; i++) {
            const int r = base + i;
            u64 ar  = s_br[r];
            u64 az  = s_bz[r];
            u64 anx = s_bnx[r];
            u64 anh = s_bnh[r];

            // h-part first (SMEM-only; overlaps the x LDGs)
            const ulonglong2* ur = (const ulonglong2*)&s_whh[r * WSTRIDE];
            const ulonglong2* uz = (const ulonglong2*)&s_whh[(HID + r) * WSTRIDE];
            const ulonglong2* un = (const ulonglong2*)&s_whh[(2 * HID + r) * WSTRIDE];
#pragma unroll
            for (int j = 0; j < HID / 2; j++) {
                ulonglong2 a = ur[j], b = uz[j], c = un[j];
                ffma2_ip(ar,  h[2*j],   a.x);
                ffma2_ip(az,  h[2*j],   b.x);
                ffma2_ip(anh, h[2*j],   c.x);
                ffma2_ip(ar,  h[2*j+1], a.y);
                ffma2_ip(az,  h[2*j+1], b.y);
                ffma2_ip(anh, h[2*j+1], c.y);
            }

            // x-part
            const ulonglong2* wr = (const ulonglong2*)&s_wih[r * WSTRIDE];
            const ulonglong2* wz = (const ulonglong2*)&s_wih[(HID + r) * WSTRIDE];
            const ulonglong2* wn = (const ulonglong2*)&s_wih[(2 * HID + r) * WSTRIDE];
#pragma unroll
            for (int f = 0; f < FIN / 2; f++) {
                ulonglong2 a = wr[f], b = wz[f], c = wn[f];
                ffma2_ip(ar,  xp[2*f],   a.x);
                ffma2_ip(az,  xp[2*f],   b.x);
                ffma2_ip(anx, xp[2*f],   c.x);
                ffma2_ip(ar,  xp[2*f+1], a.y);
                ffma2_ip(az,  xp[2*f+1], b.y);
                ffma2_ip(anx, xp[2*f+1], c.y);
            }

            float arx, ary, azx, azy, nxx, nxy, nhx, nhy, h0, h1v;
            upk(ar, arx, ary);
            upk(az, azx, azy);
            upk(anx, nxx, nxy);
            upk(anh, nhx, nhy);
            upk(h[r], h0, h1v);

            float r0 = sigmoidf_(arx), r1 = sigmoidf_(ary);
            float z0 = sigmoidf_(azx), z1 = sigmoidf_(azy);
            float n0 = tanhf_(fmaf(r0, nhx, nxx));
            float n1 = tanhf_(fmaf(r1, nhy, nxy));
            float o0 = fmaf(z0, h0 - n0, n0);
            float o1 = fmaf(z1, h1v - n1, n1);
            hn[i] = pk(o0, o1);
        }

        // Exchange new-h halves with the partner lane (lane^1, same warp).
#pragma unroll
        for (int i = 0; i < RPH; i++) {
            u64 oth = __shfl_xor_sync(0xffffffffu, hn[i], 1);
            h[base + i]  = hn[i];
            h[obase + i] = oth;
        }
    }

    // FC head: trivial work, half 0 computes both packed batch elements.
    if (half != 0) return;

    u64 h1[8];
#pragma unroll
    for (int j = 0; j < 8; j++) {
        u64 acc = s_f1b[j];
        const ulonglong2* w = (const ulonglong2*)&s_f1w[j * HID];
#pragma unroll
        for (int k = 0; k < HID / 2; k++) {
            ulonglong2 a = w[k];
            ffma2_ip(acc, h[2*k],   a.x);
            ffma2_ip(acc, h[2*k+1], a.y);
        }
        float a, b;
        upk(acc, a, b);
        h1[j] = pk(fmaxf(a, 0.0f), fmaxf(b, 0.0f));
    }

    float l0[4], l1[4];
#pragma unroll
    for (int c = 0; c < 4; c++) {
        u64 acc = s_f2b[c];
        const ulonglong2* w = (const ulonglong2*)&s_f2w[c * 8];
#pragma unroll
        for (int k = 0; k < 4; k++) {
            ulonglong2 a = w[k];
            ffma2_ip(acc, h1[2*k],   a.x);
            ffma2_ip(acc, h1[2*k+1], a.y);
        }
        upk(acc, l0[c], l1[c]);
    }

    float* o0p = out + (size_t)(2 * pair) * 4;
    float* o1p = o0p + 4;
    {
        float m = fmaxf(fmaxf(l0[0], l0[1]), fmaxf(l0[2], l0[3]));
        float e[4]; float s = 0.0f;
#pragma unroll
        for (int c = 0; c < 4; c++) { e[c] = __expf(l0[c] - m); s += e[c]; }
        float inv = __fdividef(1.0f, s);
#pragma unroll
        for (int c = 0; c < 4; c++) o0p[c] = e[c] * inv;
    }
    {
        float m = fmaxf(fmaxf(l1[0], l1[1]), fmaxf(l1[2], l1[3]));
        float e[4]; float s = 0.0f;
#pragma unroll
        for (int c = 0; c < 4; c++) { e[c] = __expf(l1[c] - m); s += e[c]; }
        float inv = __fdividef(1.0f, s);
#pragma unroll
        for (int c = 0; c < 4; c++) o1p[c] = e[c] * inv;
    }
}

extern "C" void kernel_launch(void* const* d_in, const int* in_sizes, int n_in,
                              void* d_out, int out_size) {
    const float* x     = (const float*)d_in[0];
    const float* w_ih  = (const float*)d_in[1];
    const float* w_hh  = (const float*)d_in[2];
    const float* b_ih  = (const float*)d_in[3];
    const float* b_hh  = (const float*)d_in[4];
    const float* fc1_w = (const float*)d_in[5];
    const float* fc1_b = (const float*)d_in[6];
    const float* fc2_w = (const float*)d_in[7];
    const float* fc2_b = (const float*)d_in[8];
    float* out = (float*)d_out;

    // 148 CTAs x 224 threads = 33152 threads; 32768 active (warp-aligned tail).
    // 2 threads per batch-pair (gate-split), 7 busy warps on every SM.
    dim3 grid(148), block(224);
    _ShotRNN_90417651516362_kernel<<<grid, block>>>(
        x, w_ih, w_hh, b_ih, b_hh, fc1_w, fc1_b, fc2_w, fc2_b, out);
}

// round 5
// speedup vs baseline: 1.4753x; 1.4753x over previous
#include <cuda_runtime.h>
#include <cstdint>

#define BATCH   32768
#define PAIRS   (BATCH / 2)      // 16384
#define TSTEPS  60
#define FIN     26
#define HID     24
#define RPH     (HID / 2)        // 12 rows per half-thread
#define WST     28               // padded float stride for weight rows (112B)

typedef unsigned long long u64;

// ---------- packed f32x2 helpers ----------
__device__ __forceinline__ u64 pk(float a, float b) {
    u64 r;
    asm("mov.b64 %0, {%1, %2};" : "=l"(r) : "f"(a), "f"(b));
    return r;
}
__device__ __forceinline__ void upk(u64 v, float& a, float& b) {
    asm("mov.b64 {%0, %1}, %2;" : "=f"(a), "=f"(b) : "l"(v));
}
__device__ __forceinline__ void ffma2_ip(u64& acc, u64 a, u64 b) {
    asm("fma.rn.f32x2 %0, %1, %2, %0;" : "+l"(acc) : "l"(a), "l"(b));
}
__device__ __forceinline__ float hadd(u64 v) {
    float a, b; upk(v, a, b); return a + b;
}

// ---------- fast activations (≈1e-6 rel err) ----------
__device__ __forceinline__ float sigmoidf_(float x) {
    return __fdividef(1.0f, 1.0f + __expf(-x));
}
__device__ __forceinline__ float tanhf_(float x) {
    float s = __fdividef(2.0f, 1.0f + __expf(-2.0f * x));
    return s - 1.0f;
}

__global__ void __launch_bounds__(224, 1)
_ShotRNN_90417651516362_kernel(
    const float* __restrict__ x,      // [B, T, 26]
    const float* __restrict__ w_ih,   // [72, 26]
    const float* __restrict__ w_hh,   // [72, 24]
    const float* __restrict__ b_ih,   // [72]
    const float* __restrict__ b_hh,   // [72]
    const float* __restrict__ fc1_w,  // [8, 24]
    const float* __restrict__ fc1_b,  // [8]
    const float* __restrict__ fc2_w,  // [4, 8]
    const float* __restrict__ fc2_b,  // [4]
    float* __restrict__ out)          // [B, 4]
{
    // Natural-fp32 weights, rows padded to 28 floats (112B):
    //  - 16B alignment for every row (16 | 112)
    //  - the two cooperating halves hit banks offset by 16 (12*112/4 mod 32 = 16)
    __shared__ __align__(16) float s_wih[72 * WST];
    __shared__ __align__(16) float s_whh[72 * WST];
    __shared__ __align__(16) u64 s_br[HID];    // pk(b_ih+b_hh, 0) per r-gate row
    __shared__ __align__(16) u64 s_bz[HID];
    __shared__ __align__(16) u64 s_bnx[HID];   // pk(b_ih_n, 0)
    __shared__ __align__(16) u64 s_bnh[HID];   // pk(b_hh_n, 0)
    __shared__ __align__(16) float s_f1w[8 * HID];
    __shared__ __align__(16) float s_f1b[8];
    __shared__ __align__(16) float s_f2w[4 * 8];
    __shared__ __align__(16) float s_f2b[4];

    const int tid = threadIdx.x;
    const int blk = blockDim.x;

    for (int i = tid; i < 72 * WST; i += blk) {
        int r = i / WST, c = i % WST;
        s_wih[i] = (c < FIN) ? w_ih[r * FIN + c] : 0.0f;
        s_whh[i] = (c < HID) ? w_hh[r * HID + c] : 0.0f;
    }
    for (int i = tid; i < HID; i += blk) {
        s_br[i]  = pk(b_ih[i]          + b_hh[i],          0.0f);
        s_bz[i]  = pk(b_ih[HID + i]    + b_hh[HID + i],    0.0f);
        s_bnx[i] = pk(b_ih[2*HID + i], 0.0f);
        s_bnh[i] = pk(b_hh[2*HID + i], 0.0f);
    }
    for (int i = tid; i < 8 * HID; i += blk) s_f1w[i] = fc1_w[i];
    for (int i = tid; i < 8; i += blk)       s_f1b[i] = fc1_b[i];
    for (int i = tid; i < 32; i += blk)      s_f2w[i] = fc2_w[i];
    for (int i = tid; i < 4; i += blk)       s_f2b[i] = fc2_b[i];
    __syncthreads();

    // Two consecutive lanes (2k, 2k+1) cooperate on one batch-pair;
    // half 0 owns gate rows 0-11, half 1 owns rows 12-23.
    const int worker = blockIdx.x * blk + tid;
    const int pair = worker >> 1;
    const int half = worker & 1;
    if (pair >= PAIRS) return;

    const int base = half * RPH;       // my first gate row
    const int myp  = half * 6;         // my h-pair region [myp, myp+6)
    const int otp  = 6 - myp;          // partner's h-pair region

    const float* xr0 = x + (size_t)(2 * pair) * (TSTEPS * FIN);
    const float* xr1 = xr0 + (TSTEPS * FIN);

    // h as reduction-packed pairs: hh{q}[j] = (h[2j], h[2j+1]) for batch q
    u64 hh0[RPH], hh1[RPH];
#pragma unroll
    for (int j = 0; j < RPH; j++) { hh0[j] = 0ull; hh1[j] = 0ull; }

#pragma unroll 1
    for (int t = 0; t < TSTEPS; t++) {
        // x rows as natural pairs: direct u64 loads, zero pack MOVs.
        u64 xp0[13], xp1[13];
        const u64* px0 = (const u64*)(xr0 + t * FIN);
        const u64* px1 = (const u64*)(xr1 + t * FIN);
#pragma unroll
        for (int f = 0; f < 13; f++) {
            xp0[f] = __ldg(px0 + f);
            xp1[f] = __ldg(px1 + f);
        }

        u64 hnp0[6], hnp1[6];   // my 12 new h values as 6 pairs per batch
#pragma unroll 2
        for (int p = 0; p < 6; p++) {
            // old h scalars for my rows base+2p, base+2p+1
            float ho0x, ho0y, ho1x, ho1y;
            upk(hh0[myp + p], ho0x, ho0y);
            upk(hh1[myp + p], ho1x, ho1y);

            float o0[2], o1[2];  // new h for (row s) x (batch)
#pragma unroll
            for (int s = 0; s < 2; s++) {
                const int r = base + 2 * p + s;
                u64 ar0 = s_br[r],  ar1 = ar0;
                u64 az0 = s_bz[r],  az1 = az0;
                u64 anx0 = s_bnx[r], anx1 = anx0;
                u64 anh0 = s_bnh[r], anh1 = anh0;

                // ---- h-part: 18 LDS.128, 72 FFMA2 ----
                const ulonglong2* ur = (const ulonglong2*)(s_whh + r * WST);
                const ulonglong2* uz = (const ulonglong2*)(s_whh + (HID + r) * WST);
                const ulonglong2* un = (const ulonglong2*)(s_whh + (2*HID + r) * WST);
#pragma unroll
                for (int j = 0; j < 6; j++) {
                    ulonglong2 a = ur[j], b = uz[j], c = un[j];
                    ffma2_ip(ar0,  hh0[2*j],   a.x);
                    ffma2_ip(ar1,  hh1[2*j],   a.x);
                    ffma2_ip(az0,  hh0[2*j],   b.x);
                    ffma2_ip(az1,  hh1[2*j],   b.x);
                    ffma2_ip(anh0, hh0[2*j],   c.x);
                    ffma2_ip(anh1, hh1[2*j],   c.x);
                    ffma2_ip(ar0,  hh0[2*j+1], a.y);
                    ffma2_ip(ar1,  hh1[2*j+1], a.y);
                    ffma2_ip(az0,  hh0[2*j+1], b.y);
                    ffma2_ip(az1,  hh1[2*j+1], b.y);
                    ffma2_ip(anh0, hh0[2*j+1], c.y);
                    ffma2_ip(anh1, hh1[2*j+1], c.y);
                }

                // ---- x-part: 18 LDS.128 + 3 LDS.64, 78 FFMA2 ----
                const ulonglong2* wr = (const ulonglong2*)(s_wih + r * WST);
                const ulonglong2* wz = (const ulonglong2*)(s_wih + (HID + r) * WST);
                const ulonglong2* wn = (const ulonglong2*)(s_wih + (2*HID + r) * WST);
#pragma unroll
                for (int j = 0; j < 6; j++) {
                    ulonglong2 a = wr[j], b = wz[j], c = wn[j];
                    ffma2_ip(ar0,  xp0[2*j],   a.x);
                    ffma2_ip(ar1,  xp1[2*j],   a.x);
                    ffma2_ip(az0,  xp0[2*j],   b.x);
                    ffma2_ip(az1,  xp1[2*j],   b.x);
                    ffma2_ip(anx0, xp0[2*j],   c.x);
                    ffma2_ip(anx1, xp1[2*j],   c.x);
                    ffma2_ip(ar0,  xp0[2*j+1], a.y);
                    ffma2_ip(ar1,  xp1[2*j+1], a.y);
                    ffma2_ip(az0,  xp0[2*j+1], b.y);
                    ffma2_ip(az1,  xp1[2*j+1], b.y);
                    ffma2_ip(anx0, xp0[2*j+1], c.y);
                    ffma2_ip(anx1, xp1[2*j+1], c.y);
                }
                {
                    u64 a12 = *(const u64*)(s_wih + r * WST + 24);
                    u64 b12 = *(const u64*)(s_wih + (HID + r) * WST + 24);
                    u64 c12 = *(const u64*)(s_wih + (2*HID + r) * WST + 24);
                    ffma2_ip(ar0,  xp0[12], a12);
                    ffma2_ip(ar1,  xp1[12], a12);
                    ffma2_ip(az0,  xp0[12], b12);
                    ffma2_ip(az1,  xp1[12], b12);
                    ffma2_ip(anx0, xp0[12], c12);
                    ffma2_ip(anx1, xp1[12], c12);
                }

                // ---- horizontal add + activations ----
                float a_r0 = hadd(ar0),  a_r1 = hadd(ar1);
                float a_z0 = hadd(az0),  a_z1 = hadd(az1);
                float a_x0 = hadd(anx0), a_x1 = hadd(anx1);
                float a_h0 = hadd(anh0), a_h1 = hadd(anh1);

                float rg0 = sigmoidf_(a_r0), rg1 = sigmoidf_(a_r1);
                float zg0 = sigmoidf_(a_z0), zg1 = sigmoidf_(a_z1);
                float ng0 = tanhf_(fmaf(rg0, a_h0, a_x0));
                float ng1 = tanhf_(fmaf(rg1, a_h1, a_x1));

                float hold0 = s ? ho0y : ho0x;
                float hold1 = s ? ho1y : ho1x;
                o0[s] = fmaf(zg0, hold0 - ng0, ng0);
                o1[s] = fmaf(zg1, hold1 - ng1, ng1);
            }
            hnp0[p] = pk(o0[0], o0[1]);
            hnp1[p] = pk(o1[0], o1[1]);
        }

        // Exchange halves with partner lane (lane^1, same warp).
#pragma unroll
        for (int p = 0; p < 6; p++) {
            u64 e0 = __shfl_xor_sync(0xffffffffu, hnp0[p], 1);
            u64 e1 = __shfl_xor_sync(0xffffffffu, hnp1[p], 1);
            hh0[myp + p] = hnp0[p];
            hh1[myp + p] = hnp1[p];
            hh0[otp + p] = e0;
            hh1[otp + p] = e1;
        }
    }

    // ---- FC head (half 0 computes both batch elements; trivial work) ----
    if (half != 0) return;

    float f10[8], f11[8];
#pragma unroll
    for (int j = 0; j < 8; j++) {
        u64 acc0 = 0ull, acc1 = 0ull;
        const ulonglong2* w = (const ulonglong2*)(s_f1w + j * HID);
#pragma unroll
        for (int k = 0; k < 6; k++) {
            ulonglong2 a = w[k];
            ffma2_ip(acc0, hh0[2*k],   a.x);
            ffma2_ip(acc1, hh1[2*k],   a.x);
            ffma2_ip(acc0, hh0[2*k+1], a.y);
            ffma2_ip(acc1, hh1[2*k+1], a.y);
        }
        f10[j] = fmaxf(hadd(acc0) + s_f1b[j], 0.0f);
        f11[j] = fmaxf(hadd(acc1) + s_f1b[j], 0.0f);
    }
    u64 h1p0[4], h1p1[4];
#pragma unroll
    for (int k = 0; k < 4; k++) {
        h1p0[k] = pk(f10[2*k], f10[2*k+1]);
        h1p1[k] = pk(f11[2*k], f11[2*k+1]);
    }

    float l0[4], l1[4];
#pragma unroll
    for (int c = 0; c < 4; c++) {
        u64 acc0 = 0ull, acc1 = 0ull;
        const ulonglong2* w = (const ulonglong2*)(s_f2w + c * 8);
#pragma unroll
        for (int k = 0; k < 2; k++) {
            ulonglong2 a = w[k];
            ffma2_ip(acc0, h1p0[2*k],   a.x);
            ffma2_ip(acc1, h1p1[2*k],   a.x);
            ffma2_ip(acc0, h1p0[2*k+1], a.y);
            ffma2_ip(acc1, h1p1[2*k+1], a.y);
        }
        l0[c] = hadd(acc0) + s_f2b[c];
        l1[c] = hadd(acc1) + s_f2b[c];
    }

    // ---- softmax over 4, vectorized stores ----
    float4 r0, r1;
    {
        float m = fmaxf(fmaxf(l0[0], l0[1]), fmaxf(l0[2], l0[3]));
        float e0 = __expf(l0[0] - m), e1 = __expf(l0[1] - m);
        float e2 = __expf(l0[2] - m), e3 = __expf(l0[3] - m);
        float inv = __fdividef(1.0f, e0 + e1 + e2 + e3);
        r0 = make_float4(e0 * inv, e1 * inv, e2 * inv, e3 * inv);
    }
    {
        float m = fmaxf(fmaxf(l1[0], l1[1]), fmaxf(l1[2], l1[3]));
        float e0 = __expf(l1[0] - m), e1 = __expf(l1[1] - m);
        float e2 = __expf(l1[2] - m), e3 = __expf(l1[3] - m);
        float inv = __fdividef(1.0f, e0 + e1 + e2 + e3);
        r1 = make_float4(e0 * inv, e1 * inv, e2 * inv, e3 * inv);
    }
    float4* op = (float4*)(out + (size_t)(2 * pair) * 4);
    op[0] = r0;
    op[1] = r1;
}

extern "C" void kernel_launch(void* const* d_in, const int* in_sizes, int n_in,
                              void* d_out, int out_size) {
    const float* x     = (const float*)d_in[0];
    const float* w_ih  = (const float*)d_in[1];
    const float* w_hh  = (const float*)d_in[2];
    const float* b_ih  = (const float*)d_in[3];
    const float* b_hh  = (const float*)d_in[4];
    const float* fc1_w = (const float*)d_in[5];
    const float* fc1_b = (const float*)d_in[6];
    const float* fc2_w = (const float*)d_in[7];
    const float* fc2_b = (const float*)d_in[8];
    float* out = (float*)d_out;

    dim3 grid(148), block(224);
    _ShotRNN_90417651516362_kernel<<<grid, block>>>(
        x, w_ih, w_hh, b_ih, b_hh, fc1_w, fc1_b, fc2_w, fc2_b, out);
}